// round 17
// baseline (speedup 1.0000x reference)
#include <cuda_runtime.h>
#include <cuda_fp16.h>
#include <cuda_bf16.h>
#include <mma.h>

#define BN_EPS 1e-5f
using namespace nvcuda;

// ---------------- scratch (__device__ globals; no allocation anywhere) ----------------
__device__ __align__(16) __half g_wpk[1572864]; // [3][64 i][128 slot][64 o] fp16 MMA B tiles
__device__ __align__(16) float g_fwt[16384];    // [256][64] transposed fuse weights
__device__ __align__(16) float g_ybr[1572864];  // [3][2][64][4096] raw branch conv outputs
__device__ __align__(16) float g_out0[524288];  // [2][64][4096] pre-BN fuse output
__device__ float g_xmean[128];
__device__ float g_bna[192];
__device__ float g_bnc[192];
__device__ float g_sered[384];
__device__ float g_scale[384];
__device__ float g_gpterm[128];
__device__ float g_fa[64];
__device__ float g_fc[64];

__device__ __forceinline__ float sigmoidf_(float v) {
    return __fdividef(1.f, 1.f + __expf(-v));
}

__device__ __forceinline__ float block_reduce(float v, float* sbuf) {
    int tid = threadIdx.x;
    sbuf[tid] = v;
    __syncthreads();
    for (int st = blockDim.x >> 1; st > 0; st >>= 1) {
        if (tid < st) sbuf[tid] += sbuf[tid + st];
        __syncthreads();
    }
    float r = sbuf[0];
    __syncthreads();
    return r;
}

// ---------------- weight repack into dense MMA B tiles ----------------
// slot layout per (i): k*RPK + r; r=0,1: base_w (silu hi/lo rows), r=2+jr: spline_w[jr],
// jr in [0, G+2]. RPK = G+5. slots >= 9*RPK are zero. Stored [slot][o], fp16.
__global__ void pack_kernel(const float* __restrict__ bw0, const float* __restrict__ sw0,
                            const float* __restrict__ bw1, const float* __restrict__ sw1,
                            const float* __restrict__ bw2, const float* __restrict__ sw2,
                            const float* __restrict__ fw) {
    int stride = gridDim.x * blockDim.x;
    int t0 = blockIdx.x * blockDim.x + threadIdx.x;
    for (int idx = t0; idx < 1572864; idx += stride) {
        int o = idx & 63;
        int t = idx >> 6;
        int slot = t & 127; t >>= 7;
        int i = t & 63;
        int br = t >> 6;
        int G = 3 * (br + 1);
        int RPK = G + 5;
        float v = 0.f;
        if (slot < 9 * RPK) {
            int k = slot / RPK, r = slot - k * RPK;
            const float* bw = (br == 0) ? bw0 : ((br == 1) ? bw1 : bw2);
            const float* sw = (br == 0) ? sw0 : ((br == 1) ? sw1 : sw2);
            if (r < 2) v = bw[(o * 64 + i) * 9 + k];
            else       v = sw[((o * 64 + i) * 9 + k) * (G + 3) + (r - 2)];
        }
        g_wpk[idx] = __float2half(v);
    }
    for (int idx = t0; idx < 16384; idx += stride) {
        int o = idx & 63; int ch = idx >> 6;
        g_fwt[idx] = fw[o * 256 + ch];
    }
}

// ---------------- x channel means (gp branch) ----------------
__global__ void xmean_kernel(const float* __restrict__ x) {
    __shared__ float sbuf[128];
    int bi = blockIdx.x;
    const float4* p = (const float4*)(x + bi * 4096);
    float s = 0.f;
    for (int j = threadIdx.x; j < 1024; j += 128) {
        float4 v = p[j];
        s += (v.x + v.y) + (v.z + v.w);
    }
    s = block_reduce(s, sbuf);
    if (threadIdx.x == 0) g_xmean[bi] = s * (1.f / 4096.f);
}

// ---------------- KAN conv as wmma implicit GEMM ----------------
// CTA: one image row (64 px) of one (branch, batch). Per channel i: producers
// build fp16 basis tile A[64 px][Kpad] (dense cardinal-cubic slots + silu hi/lo),
// copy pre-packed B[Kpad][64 o], then 4 warps wmma-accumulate C[64][64] in fp32.
__global__ void __launch_bounds__(128) conv_tc_kernel(const float* __restrict__ x) {
    __shared__ __half sB[8192];   // [slot][o]
    __shared__ __half sA[8192];   // [px][Kpad]
    __shared__ float sXs[192];    // 3 h-rows x 64 w
    int h = blockIdx.x, b = blockIdx.y, br = blockIdx.z;
    int d = 6 * (br + 1), G = 3 * (br + 1);
    int RPK = G + 5;
    int Kpad = (br == 0) ? 80 : (br == 1) ? 112 : 128;
    float invh = 0.5f * (float)G;
    float s0 = invh + 3.f;
    float smax = (float)(G + 6);
    int tid = threadIdx.x, wid = tid >> 5;
    const float* xb = x + b * 262144;
    const __half* wsrc = g_wpk + (br * 64) * 8192;

    wmma::fragment<wmma::accumulator, 16, 16, 16, float> fc[4];
#pragma unroll
    for (int n = 0; n < 4; n++) wmma::fill_fragment(fc[n], 0.f);

    int nV = Kpad << 3;   // uint4 count for Kpad*64 halves
#pragma unroll 1
    for (int i = 0; i < 64; i++) {
        const uint4* bsrc = (const uint4*)(wsrc + i * 8192);
        for (int j = tid; j < nV; j += 128) ((uint4*)sB)[j] = bsrc[j];
        uint4 z4 = make_uint4(0, 0, 0, 0);
        for (int j = tid; j < nV; j += 128) ((uint4*)sA)[j] = z4;
        for (int j = tid; j < 192; j += 128) {
            int ki = j >> 6, w = j & 63;
            int hh = h + (ki - 1) * d;
            sXs[j] = ((unsigned)hh < 64u) ? xb[i * 4096 + hh * 64 + w] : 0.f;
        }
        __syncthreads();

        // fill basis taps: 9 k x 64 px
        for (int j = tid; j < 576; j += 128) {
            int k = j >> 6, w = j & 63;
            int ki = k / 3, kj = k - ki * 3;
            int ww = w + (kj - 1) * d;
            float v = ((unsigned)ww < 64u) ? sXs[ki * 64 + ww] : 0.f;
            float e = __expf(-v);
            float silu = __fdividef(v, 1.f + e);
            __half shi = __float2half(silu);
            float slo = silu - __half2float(shi);
            __half* Ar = sA + w * Kpad + k * RPK;
            Ar[0] = shi;
            Ar[1] = __float2half(slo);
            float s = fmaf(v, invh, s0);
            float mf = floorf(s);
            float u = s - mf;
            float msk = (s >= 0.f && s < smax) ? (1.f / 6.f) : 0.f;
            int mi = min(max((int)mf, 0), G + 5);
            float u2 = u * u, u3 = u2 * u, om = 1.f - u;
            float c0 = om * om * om * msk;
            float c1 = (3.f * u3 - 6.f * u2 + 4.f) * msk;
            float c2 = (-3.f * u3 + 3.f * u2 + 3.f * u + 1.f) * msk;
            float c3 = u3 * msk;
            int base = mi - 3;
            if ((unsigned)(base + 0) <= (unsigned)(G + 2)) Ar[2 + base + 0] = __float2half(c0);
            if ((unsigned)(base + 1) <= (unsigned)(G + 2)) Ar[2 + base + 1] = __float2half(c1);
            if ((unsigned)(base + 2) <= (unsigned)(G + 2)) Ar[2 + base + 2] = __float2half(c2);
            if ((unsigned)(base + 3) <= (unsigned)(G + 2)) Ar[2 + base + 3] = __float2half(c3);
        }
        __syncthreads();

        int nks = Kpad >> 4;
        for (int ks = 0; ks < nks; ks++) {
            wmma::fragment<wmma::matrix_a, 16, 16, 16, __half, wmma::row_major> fa;
            wmma::load_matrix_sync(fa, sA + (wid << 4) * Kpad + (ks << 4), Kpad);
#pragma unroll
            for (int n = 0; n < 4; n++) {
                wmma::fragment<wmma::matrix_b, 16, 16, 16, __half, wmma::row_major> fb;
                wmma::load_matrix_sync(fb, sB + (ks << 4) * 64 + (n << 4), 64);
                wmma::mma_sync(fc[n], fa, fb, fc[n]);
            }
        }
        __syncthreads();
    }

    // store C as [o][px] (col-major) then write coalesced
    float* sC = (float*)sB;
#pragma unroll
    for (int n = 0; n < 4; n++)
        wmma::store_matrix_sync(sC + (n << 4) * 64 + (wid << 4), fc[n], 64, wmma::mem_col_major);
    __syncthreads();
    int z64 = (br * 2 + b) * 64;
    for (int j = tid; j < 4096; j += 128) {
        int o = j >> 6, w = j & 63;
        g_ybr[(z64 + o) * 4096 + h * 64 + w] = sC[j];
    }
}

// ---------------- per-branch BN stats ----------------
__global__ void bnstats_kernel(const float* __restrict__ g6, const float* __restrict__ bb6,
                               const float* __restrict__ g12, const float* __restrict__ bb12,
                               const float* __restrict__ g18, const float* __restrict__ bb18) {
    __shared__ float sbuf[256];
    int o = blockIdx.x, br = blockIdx.y;
    const float4* p0 = (const float4*)(g_ybr + ((br * 2 + 0) * 64 + o) * 4096);
    const float4* p1 = (const float4*)(g_ybr + ((br * 2 + 1) * 64 + o) * 4096);
    float s = 0.f, sq = 0.f;
    for (int j = threadIdx.x; j < 1024; j += 256) {
        float4 v0 = p0[j], v1 = p1[j];
        s += (v0.x + v0.y) + (v0.z + v0.w) + (v1.x + v1.y) + (v1.z + v1.w);
        sq += v0.x * v0.x + v0.y * v0.y + v0.z * v0.z + v0.w * v0.w
            + v1.x * v1.x + v1.y * v1.y + v1.z * v1.z + v1.w * v1.w;
    }
    s = block_reduce(s, sbuf);
    sq = block_reduce(sq, sbuf);
    if (threadIdx.x == 0) {
        float mean = s * (1.f / 8192.f);
        float var = sq * (1.f / 8192.f) - mean * mean;
        const float* gg = (br == 0) ? g6 : ((br == 1) ? g12 : g18);
        const float* bb = (br == 0) ? bb6 : ((br == 1) ? bb12 : bb18);
        float a = gg[o] * rsqrtf(var + BN_EPS);
        g_bna[br * 64 + o] = a;
        g_bnc[br * 64 + o] = bb[o] - mean * a;
    }
}

// ---------------- SE spatial reduce ----------------
__global__ void sered_kernel() {
    __shared__ float sbuf[128];
    int o = blockIdx.x, b = blockIdx.y, br = blockIdx.z;
    const float4* p = (const float4*)(g_ybr + ((br * 2 + b) * 64 + o) * 4096);
    float a = g_bna[br * 64 + o], c = g_bnc[br * 64 + o];
    float s = 0.f;
    for (int j = threadIdx.x; j < 1024; j += 128) {
        float4 v = p[j];
        s += fmaxf(fmaf(v.x, a, c), 0.f) + fmaxf(fmaf(v.y, a, c), 0.f)
           + fmaxf(fmaf(v.z, a, c), 0.f) + fmaxf(fmaf(v.w, a, c), 0.f);
    }
    s = block_reduce(s, sbuf);
    if (threadIdx.x == 0) g_sered[(br * 2 + b) * 64 + o] = s * (1.f / 4096.f);
}

// ---------------- SE MLPs + full gp branch + gp fuse term ----------------
__global__ void small_kernel(const float* __restrict__ w1_0, const float* __restrict__ w2_0,
                             const float* __restrict__ w1_1, const float* __restrict__ w2_1,
                             const float* __restrict__ w1_2, const float* __restrict__ w2_2,
                             const float* __restrict__ gpw, const float* __restrict__ gpb,
                             const float* __restrict__ gpg, const float* __restrict__ gpbeta,
                             const float* __restrict__ gpse1, const float* __restrict__ gpse2,
                             const float* __restrict__ fw) {
    __shared__ float sT[24];
    __shared__ float sGp0[128];
    __shared__ float sZ[128];
    __shared__ float sT2[8];
    __shared__ float sGpv[128];
    int tid = threadIdx.x;

    if (tid < 24) {
        int br = tid >> 3;
        int rem = tid & 7;
        int b = rem >> 2, j = rem & 3;
        const float* w1 = (br == 0) ? w1_0 : ((br == 1) ? w1_1 : w1_2);
        float v = 0.f;
        for (int o2 = 0; o2 < 64; o2++) v += g_sered[(br * 2 + b) * 64 + o2] * w1[j * 64 + o2];
        sT[tid] = fmaxf(v, 0.f);
    }
    {
        int b = tid >> 6, o = tid & 63;
        float v = gpb[o];
        for (int i = 0; i < 64; i++) v += g_xmean[b * 64 + i] * gpw[o * 64 + i];
        sGp0[tid] = v;
    }
    __syncthreads();

    if (tid < 64) {
        int o = tid;
        for (int br = 0; br < 3; br++) {
            const float* w2 = (br == 0) ? w2_0 : ((br == 1) ? w2_1 : w2_2);
            for (int b = 0; b < 2; b++) {
                float v = 0.f;
                for (int j = 0; j < 4; j++) v += sT[br * 8 + b * 4 + j] * w2[o * 4 + j];
                g_scale[(br * 2 + b) * 64 + o] = sigmoidf_(v);
            }
        }
        float a0 = sGp0[o], a1 = sGp0[64 + o];
        float m = 0.5f * (a0 + a1);
        float dv = a0 - m;
        float var = dv * dv;
        float rs = gpg[o] * rsqrtf(var + BN_EPS);
        sZ[o]      = fmaxf((a0 - m) * rs + gpbeta[o], 0.f);
        sZ[64 + o] = fmaxf((a1 - m) * rs + gpbeta[o], 0.f);
    }
    __syncthreads();

    if (tid < 8) {
        int b = tid >> 2, j = tid & 3;
        float v = 0.f;
        for (int o2 = 0; o2 < 64; o2++) v += sZ[b * 64 + o2] * gpse1[j * 64 + o2];
        sT2[tid] = fmaxf(v, 0.f);
    }
    __syncthreads();

    {
        int b = tid >> 6, o = tid & 63;
        float v = 0.f;
        for (int j = 0; j < 4; j++) v += sT2[b * 4 + j] * gpse2[o * 4 + j];
        sGpv[tid] = sZ[tid] * sigmoidf_(v);
    }
    __syncthreads();

    {
        int b = tid >> 6, oo = tid & 63;
        float v = 0.f;
        for (int i = 0; i < 64; i++) v += fw[oo * 256 + 192 + i] * sGpv[b * 64 + i];
        g_gpterm[tid] = v;
    }
}

// ---------------- fuse 1x1 conv ----------------
__global__ void __launch_bounds__(128) fuse_kernel(const float* __restrict__ fuse_b) {
    __shared__ float sCat[192][32];
    int b = blockIdx.z, h = blockIdx.y, w0 = blockIdx.x << 5;
    int tid = threadIdx.x;

    for (int j = tid; j < 1536; j += 128) {
        int ch = j >> 3, p4 = (j & 7) << 2;
        int br = ch >> 6, i = ch & 63;
        float4 v = *(const float4*)(g_ybr + ((br * 2 + b) * 64 + i) * 4096 + h * 64 + w0 + p4);
        float a = g_bna[br * 64 + i], c = g_bnc[br * 64 + i];
        float sc = g_scale[(br * 2 + b) * 64 + i];
        float4 r;
        r.x = fmaxf(fmaf(v.x, a, c), 0.f) * sc;
        r.y = fmaxf(fmaf(v.y, a, c), 0.f) * sc;
        r.z = fmaxf(fmaf(v.z, a, c), 0.f) * sc;
        r.w = fmaxf(fmaf(v.w, a, c), 0.f) * sc;
        *(float4*)&sCat[ch][p4] = r;
    }
    __syncthreads();

    int warpId = tid >> 5, lane = tid & 31;
    int o = ((warpId & 1) << 5) | lane;
    int ph = warpId >> 1;
    float acc[16];
    float init = g_gpterm[b * 64 + o] + fuse_b[o];
#pragma unroll
    for (int p = 0; p < 16; p++) acc[p] = init;

#pragma unroll 1
    for (int ch = 0; ch < 192; ch++) {
        float fwv = g_fwt[(ch << 6) + o];
#pragma unroll
        for (int p = 0; p < 16; p++)
            acc[p] = fmaf(fwv, sCat[ch][(ph << 4) + p], acc[p]);
    }

    int base = (b * 64 + o) * 4096 + h * 64 + w0 + (ph << 4);
#pragma unroll
    for (int p = 0; p < 16; p++) g_out0[base + p] = acc[p];
}

// ---------------- fuse BN stats ----------------
__global__ void fstats_kernel(const float* __restrict__ fg, const float* __restrict__ fb) {
    __shared__ float sbuf[256];
    int o = blockIdx.x;
    const float4* p0 = (const float4*)(g_out0 + o * 4096);
    const float4* p1 = (const float4*)(g_out0 + (64 + o) * 4096);
    float s = 0.f, sq = 0.f;
    for (int j = threadIdx.x; j < 1024; j += 256) {
        float4 v0 = p0[j], v1 = p1[j];
        s += (v0.x + v0.y) + (v0.z + v0.w) + (v1.x + v1.y) + (v1.z + v1.w);
        sq += v0.x * v0.x + v0.y * v0.y + v0.z * v0.z + v0.w * v0.w
            + v1.x * v1.x + v1.y * v1.y + v1.z * v1.z + v1.w * v1.w;
    }
    s = block_reduce(s, sbuf);
    sq = block_reduce(sq, sbuf);
    if (threadIdx.x == 0) {
        float mean = s * (1.f / 8192.f);
        float var = sq * (1.f / 8192.f) - mean * mean;
        float a = fg[o] * rsqrtf(var + BN_EPS);
        g_fa[o] = a;
        g_fc[o] = fb[o] - mean * a;
    }
}

// ---------------- final elementwise ----------------
__global__ void final_kernel(float* __restrict__ out) {
    int idx = blockIdx.x * blockDim.x + threadIdx.x;
    if (idx >= 131072) return;
    int o = (idx >> 10) & 63;
    float a = g_fa[o], c = g_fc[o];
    float4 v = ((const float4*)g_out0)[idx];
    float4 r;
    r.x = fmaxf(fmaf(v.x, a, c), 0.f);
    r.y = fmaxf(fmaf(v.y, a, c), 0.f);
    r.z = fmaxf(fmaf(v.z, a, c), 0.f);
    r.w = fmaxf(fmaf(v.w, a, c), 0.f);
    ((float4*)out)[idx] = r;
}

// ---------------- launch ----------------
extern "C" void kernel_launch(void* const* d_in, const int* in_sizes, int n_in,
                              void* d_out, int out_size) {
    const float* x       = (const float*)d_in[0];
    const float* bw6     = (const float*)d_in[1];
    const float* sw6     = (const float*)d_in[2];
    const float* bn6_g   = (const float*)d_in[3];
    const float* bn6_b   = (const float*)d_in[4];
    const float* se6_w1  = (const float*)d_in[5];
    const float* se6_w2  = (const float*)d_in[6];
    const float* bw12    = (const float*)d_in[7];
    const float* sw12    = (const float*)d_in[8];
    const float* bn12_g  = (const float*)d_in[9];
    const float* bn12_b  = (const float*)d_in[10];
    const float* se12_w1 = (const float*)d_in[11];
    const float* se12_w2 = (const float*)d_in[12];
    const float* bw18    = (const float*)d_in[13];
    const float* sw18    = (const float*)d_in[14];
    const float* bn18_g  = (const float*)d_in[15];
    const float* bn18_b  = (const float*)d_in[16];
    const float* se18_w1 = (const float*)d_in[17];
    const float* se18_w2 = (const float*)d_in[18];
    const float* gp_w    = (const float*)d_in[19];
    const float* gp_b    = (const float*)d_in[20];
    const float* gp_bn_g = (const float*)d_in[21];
    const float* gp_bn_b = (const float*)d_in[22];
    const float* gp_se1  = (const float*)d_in[23];
    const float* gp_se2  = (const float*)d_in[24];
    const float* fuse_w  = (const float*)d_in[25];
    const float* fuse_b  = (const float*)d_in[26];
    const float* fbn_g   = (const float*)d_in[27];
    const float* fbn_b   = (const float*)d_in[28];
    float* out = (float*)d_out;

    pack_kernel<<<768, 256>>>(bw6, sw6, bw12, sw12, bw18, sw18, fuse_w);
    xmean_kernel<<<128, 128>>>(x);
    conv_tc_kernel<<<dim3(64, 2, 3), 128>>>(x);
    bnstats_kernel<<<dim3(64, 3), 256>>>(bn6_g, bn6_b, bn12_g, bn12_b, bn18_g, bn18_b);
    sered_kernel<<<dim3(64, 2, 3), 128>>>();
    small_kernel<<<1, 128>>>(se6_w1, se6_w2, se12_w1, se12_w2, se18_w1, se18_w2,
                             gp_w, gp_b, gp_bn_g, gp_bn_b, gp_se1, gp_se2, fuse_w);
    fuse_kernel<<<dim3(2, 64, 2), 128>>>(fuse_b);
    fstats_kernel<<<64, 256>>>(fbn_g, fbn_b);
    final_kernel<<<512, 256>>>(out);
}